// round 2
// baseline (speedup 1.0000x reference)
#include <cuda_runtime.h>
#include <math.h>

// ---------------------------------------------------------------------------
// Adaptive1DLUTNet: resize(1024->256) -> 4x strided conv+SiLU -> multi-scale
// avg-pool concat -> 3x3 conv (480->128) + SiLU -> 1x1 conv (128->27) +
// sigmoid -> bilinear upsample 8->1024 -> per-pixel 1D-LUT blend -> clip.
// ---------------------------------------------------------------------------

#define DINL __device__ __forceinline__

DINL float silu_f(float x) { return x / (1.f + expf(-x)); }
DINL float sigm_f(float x) { return 1.f / (1.f + expf(-x)); }

// ------------------------- scratch (device globals) ------------------------
__device__ float g_x[2 * 3 * 256 * 256];        // resized input
__device__ float g_c1[2 * 32 * 128 * 128];
__device__ float g_c2[2 * 64 * 64 * 64];
__device__ float g_c3[2 * 128 * 32 * 32];
__device__ float g_c4[2 * 256 * 16 * 16];
__device__ float g_feat[2 * 480 * 8 * 8];
__device__ float g_h1[2 * 128 * 8 * 8];
__device__ float g_wl[2 * 27 * 8 * 8];
__device__ float g_wT[4320 * 128];              // lin1 weights transposed [k][oc]
__device__ float g_lpart[30 * 2 * 128 * 8 * 8]; // lin1 split-K partials
__device__ float g_cpart[4 * 131072];           // conv3/conv4 split-K partials (max 524288)

// ------------------------------ resize 1024->256 ---------------------------
__global__ void resize256_kernel(const float* __restrict__ img, float* __restrict__ out) {
    int idx = blockIdx.x * blockDim.x + threadIdx.x;
    if (idx >= 2 * 3 * 256 * 256) return;
    int ox = idx & 255;
    int oy = (idx >> 8) & 255;
    int bc = idx >> 16;  // b*3+c
    const float scale = 1023.0f / 255.0f;
    float py = oy * scale;
    int iy = (int)py; if (iy > 1022) iy = 1022;
    float fy = py - (float)iy;
    float px = ox * scale;
    int ix = (int)px; if (ix > 1022) ix = 1022;
    float fx = px - (float)ix;
    const float* p = img + ((long)bc << 20) + iy * 1024 + ix;
    float v00 = p[0], v01 = p[1], v10 = p[1024], v11 = p[1025];
    float c0 = v00 + fy * (v10 - v00);
    float c1 = v01 + fy * (v11 - v01);
    out[idx] = c0 + fx * (c1 - c0);
}

// --------------------- stride-2 3x3 conv, reflect pad 1 --------------------
// Register tile: 8 oc x 4 ow per thread. Optional split-K over blockIdx.y.
template <int ICC, int OC, int H, bool FUSE>
__global__ __launch_bounds__(256) void conv3x3_s2_kernel(
    const float* __restrict__ in, const float* __restrict__ wgt,
    const float* __restrict__ bias, float* __restrict__ out, int ICtot) {
    constexpr int OH = H / 2;
    constexpr int OW = H / 2;
    constexpr int QW = OW / 4;
    constexpr int TOTAL = 2 * (OC / 8) * OH * QW;
    constexpr int NOUT = 2 * OC * OH * OW;
    int idx = blockIdx.x * blockDim.x + threadIdx.x;
    if (idx >= TOTAL) return;
    int ks = blockIdx.y;
    int ic0 = ks * ICC;

    int q = idx % QW;
    int oh = (idx / QW) % OH;
    int ocg = (idx / (QW * OH)) % (OC / 8);
    int b = idx / (QW * OH * (OC / 8));
    int ow0 = q * 4;
    int oc0 = ocg * 8;

    int rr[3];
#pragma unroll
    for (int kh = 0; kh < 3; kh++) { int r = 2 * oh - 1 + kh; rr[kh] = (r < 0) ? -r : r; }
    int cc[9];
#pragma unroll
    for (int i = 0; i < 9; i++) { int c = 2 * ow0 - 1 + i; cc[i] = (c < 0) ? -c : c; }

    float acc[8][4];
#pragma unroll
    for (int o = 0; o < 8; o++) {
        float bv = (ks == 0) ? bias[oc0 + o] : 0.f;
#pragma unroll
        for (int j = 0; j < 4; j++) acc[o][j] = bv;
    }

    for (int ic = 0; ic < ICC; ic++) {
        const float* ip = in + ((long)(b * ICtot + ic0 + ic)) * H * H;
        const float* wp = wgt + ((long)oc0 * ICtot + (ic0 + ic)) * 9;
#pragma unroll
        for (int kh = 0; kh < 3; kh++) {
            const float* rp = ip + rr[kh] * H;
            float xv[9];
#pragma unroll
            for (int i = 0; i < 9; i++) xv[i] = __ldg(rp + cc[i]);
#pragma unroll
            for (int kw = 0; kw < 3; kw++) {
#pragma unroll
                for (int o = 0; o < 8; o++) {
                    float wv = __ldg(wp + o * ICtot * 9 + kh * 3 + kw);
#pragma unroll
                    for (int j = 0; j < 4; j++) acc[o][j] += wv * xv[2 * j + kw];
                }
            }
        }
    }

#pragma unroll
    for (int o = 0; o < 8; o++) {
        int obase = (((b * OC) + (oc0 + o)) * OH + oh) * OW + ow0;
        if (FUSE) {
#pragma unroll
            for (int j = 0; j < 4; j++) out[obase + j] = silu_f(acc[o][j]);
        } else {
#pragma unroll
            for (int j = 0; j < 4; j++) out[ks * NOUT + obase + j] = acc[o][j];
        }
    }
}

// ----------------------- split-K reduce + SiLU epilogue ---------------------
__global__ void reduce_silu_kernel(const float* __restrict__ part, float* __restrict__ out,
                                   int n, int ks) {
    int idx = blockIdx.x * blockDim.x + threadIdx.x;
    if (idx >= n) return;
    float s = 0.f;
    for (int k = 0; k < ks; k++) s += part[k * n + idx];
    out[idx] = silu_f(s);
}

// ------------------------------ avg pool (warp/out) -------------------------
__global__ void pool_kernel(const float* __restrict__ in, float* __restrict__ feat,
                            int C, int H, int k, int coff) {
    int gw = (blockIdx.x * blockDim.x + threadIdx.x) >> 5;
    int lane = threadIdx.x & 31;
    int nout = 2 * C * 64;
    if (gw >= nout) return;
    int x = gw & 7;
    int y = (gw >> 3) & 7;
    int c = (gw >> 6) % C;
    int b = gw / (C * 64);
    const float* base = in + ((long)(b * C + c) * H + y * k) * H + x * k;
    float s = 0.f;
    int kk = k * k;
    for (int i = lane; i < kk; i += 32) s += base[(i / k) * H + (i % k)];
#pragma unroll
    for (int off = 16; off > 0; off >>= 1) s += __shfl_down_sync(0xffffffffu, s, off);
    if (lane == 0) feat[((b * 480 + coff + c) * 8 + y) * 8 + x] = s * (1.f / (float)kk);
}

// --------------------------- lin1 weight transpose --------------------------
__global__ void transpose_kernel(const float* __restrict__ w, float* __restrict__ wT) {
    __shared__ float tile[32][33];
    int bx = blockIdx.x;  // 135 tiles over K=4320
    int by = blockIdx.y;  // 4 tiles over OC=128
    int tx = threadIdx.x, ty = threadIdx.y;
#pragma unroll
    for (int i = 0; i < 4; i++)
        tile[ty + i * 8][tx] = w[(long)(by * 32 + ty + i * 8) * 4320 + bx * 32 + tx];
    __syncthreads();
#pragma unroll
    for (int i = 0; i < 4; i++)
        wT[(long)(bx * 32 + ty + i * 8) * 128 + by * 32 + tx] = tile[tx][ty + i * 8];
}

// ----------------- lin1: 3x3 reflect conv 480->128 on 8x8 -------------------
// Block = (kchunk of 16 ic, output row oh, batch b); 128 threads = 128 oc.
__global__ __launch_bounds__(128) void lin1_kernel(const float* __restrict__ feat,
                                                   const float* __restrict__ wT,
                                                   float* __restrict__ part) {
    __shared__ float slab[16 * 3 * 8];
    int kc = blockIdx.x;      // 0..29
    int oh = blockIdx.y;      // 0..7
    int b = blockIdx.z;       // 0..1
    int t = threadIdx.x;      // oc
    int ic0 = kc * 16;

    int ihs[3];
#pragma unroll
    for (int kh = 0; kh < 3; kh++) {
        int r = oh - 1 + kh;
        if (r < 0) r = -r;
        if (r > 7) r = 14 - r;
        ihs[kh] = r;
    }
    for (int j = t; j < 384; j += 128) {
        int icl = j / 24;
        int rem = j % 24;
        int r = rem / 8, col = rem % 8;
        slab[j] = feat[((b * 480 + ic0 + icl) * 8 + ihs[r]) * 8 + col];
    }
    __syncthreads();

    float acc[8];
#pragma unroll
    for (int ow = 0; ow < 8; ow++) acc[ow] = 0.f;

    const int IWT[10] = {1, 0, 1, 2, 3, 4, 5, 6, 7, 6};  // reflect(ow-1+kw) via p=ow+kw
#pragma unroll 2
    for (int icl = 0; icl < 16; icl++) {
        float rv[3][8];
#pragma unroll
        for (int r = 0; r < 3; r++)
#pragma unroll
            for (int col = 0; col < 8; col++) rv[r][col] = slab[icl * 24 + r * 8 + col];
#pragma unroll
        for (int kh = 0; kh < 3; kh++)
#pragma unroll
            for (int kw = 0; kw < 3; kw++) {
                float wv = __ldg(wT + (long)((ic0 + icl) * 9 + kh * 3 + kw) * 128 + t);
#pragma unroll
                for (int ow = 0; ow < 8; ow++) acc[ow] += wv * rv[kh][IWT[ow + kw]];
            }
    }
    int base = (((kc * 2 + b) * 128 + t) * 8 + oh) * 8;
#pragma unroll
    for (int ow = 0; ow < 8; ow++) part[base + ow] = acc[ow];
}

__global__ void lin1_reduce_kernel(const float* __restrict__ part,
                                   const float* __restrict__ bias, float* __restrict__ h1) {
    int idx = blockIdx.x * blockDim.x + threadIdx.x;
    if (idx >= 16384) return;
    int oc = (idx >> 6) & 127;
    float s = bias[oc];
#pragma unroll 6
    for (int kc = 0; kc < 30; kc++) s += part[kc * 16384 + idx];
    h1[idx] = silu_f(s);
}

// ------------------- lin2: 1x1 conv 128->27 + sigmoid -----------------------
__global__ void lin2_kernel(const float* __restrict__ h1, const float* __restrict__ w,
                            const float* __restrict__ bias, float* __restrict__ wl) {
    int idx = blockIdx.x * blockDim.x + threadIdx.x;
    if (idx >= 2 * 27 * 64) return;
    int pos = idx % 64;
    int oc = (idx / 64) % 27;
    int b = idx / (64 * 27);
    float acc = bias[oc];
    const float* hp = h1 + b * 128 * 64 + pos;
    const float* wp = w + oc * 128;
#pragma unroll 8
    for (int ic = 0; ic < 128; ic++) acc += hp[ic * 64] * __ldg(wp + ic);
    wl[(b * 27 + oc) * 64 + pos] = sigm_f(acc);
}

// -------- final: upsample weights 8->1024 (bilinear AC) + LUT blend ----------
__global__ __launch_bounds__(256) void final_kernel(const float* __restrict__ img,
                                                    const float* __restrict__ wl,
                                                    const float* __restrict__ luts,
                                                    float* __restrict__ out) {
    __shared__ float s_lut[3 * 9 * 256];
    __shared__ float s_row[27 * 8];  // H-interpolated weight rows for this output row

    int h = blockIdx.x;      // 0..1023
    int chunk = blockIdx.y;  // 0..3
    int b = blockIdx.z;      // 0..1
    int tid = threadIdx.x;

    for (int j = tid; j < 3 * 9 * 256; j += 256) s_lut[j] = luts[j];

    const float sc = 7.0f / 1023.0f;
    float ph = h * sc;
    int ih0 = (int)ph; if (ih0 > 6) ih0 = 6;
    float fh = ph - (float)ih0;
    if (tid < 216) {
        int ch = tid >> 3;
        int iw = tid & 7;
        float a = wl[((b * 27 + ch) * 8 + ih0) * 8 + iw];
        float c = wl[((b * 27 + ch) * 8 + ih0 + 1) * 8 + iw];
        s_row[tid] = a + fh * (c - a);
    }
    __syncthreads();

    int w = chunk * 256 + tid;
    float pw = w * sc;
    int iw0 = (int)pw; if (iw0 > 6) iw0 = 6;
    float fw = pw - (float)iw0;

#pragma unroll
    for (int c = 0; c < 3; c++) {
        long ibase = ((long)(b * 3 + c) << 20) + ((long)h << 10) + w;
        float v = img[ibase];
        float p = fminf(fmaxf(v, 0.f), 1.f) * 255.0f;
        int i0 = (int)p; if (i0 > 254) i0 = 254;
        float fr = p - (float)i0;
        float acc = 0.f;
#pragma unroll
        for (int k = 0; k < 9; k++) {
            int ch = c * 9 + k;
            float l0 = s_lut[ch * 256 + i0];
            float l1 = s_lut[ch * 256 + i0 + 1];
            float lv = l0 + fr * (l1 - l0);
            float r0 = s_row[ch * 8 + iw0];
            float r1 = s_row[ch * 8 + iw0 + 1];
            float wv = r0 + fw * (r1 - r0);
            acc += wv * lv;
        }
        out[ibase] = fminf(fmaxf(acc, 0.f), 1.f);
    }
}

// --------------------------------- launch ----------------------------------
extern "C" void kernel_launch(void* const* d_in, const int* in_sizes, int n_in,
                              void* d_out, int out_size) {
    const float* img     = (const float*)d_in[0];
    const float* conv1_w = (const float*)d_in[1];
    const float* conv1_b = (const float*)d_in[2];
    const float* conv2_w = (const float*)d_in[3];
    const float* conv2_b = (const float*)d_in[4];
    const float* conv3_w = (const float*)d_in[5];
    const float* conv3_b = (const float*)d_in[6];
    const float* conv4_w = (const float*)d_in[7];
    const float* conv4_b = (const float*)d_in[8];
    const float* lin1_w  = (const float*)d_in[9];
    const float* lin1_b  = (const float*)d_in[10];
    const float* lin2_w  = (const float*)d_in[11];
    const float* lin2_b  = (const float*)d_in[12];
    const float* luts    = (const float*)d_in[13];
    float* out = (float*)d_out;

    float *px, *pc1, *pc2, *pc3, *pc4, *pfeat, *ph1, *pwl, *pwT, *plp, *pcp;
    cudaGetSymbolAddress((void**)&px, g_x);
    cudaGetSymbolAddress((void**)&pc1, g_c1);
    cudaGetSymbolAddress((void**)&pc2, g_c2);
    cudaGetSymbolAddress((void**)&pc3, g_c3);
    cudaGetSymbolAddress((void**)&pc4, g_c4);
    cudaGetSymbolAddress((void**)&pfeat, g_feat);
    cudaGetSymbolAddress((void**)&ph1, g_h1);
    cudaGetSymbolAddress((void**)&pwl, g_wl);
    cudaGetSymbolAddress((void**)&pwT, g_wT);
    cudaGetSymbolAddress((void**)&plp, g_lpart);
    cudaGetSymbolAddress((void**)&pcp, g_cpart);

    // 1. resize 1024 -> 256
    resize256_kernel<<<1536, 256>>>(img, px);

    // 2-5. conv stack (stride-2, reflect pad, SiLU)
    conv3x3_s2_kernel<3, 32, 256, true><<<dim3(128, 1), 256>>>(px, conv1_w, conv1_b, pc1, 3);
    conv3x3_s2_kernel<32, 64, 128, true><<<dim3(64, 1), 256>>>(pc1, conv2_w, conv2_b, pc2, 32);
    conv3x3_s2_kernel<32, 128, 64, false><<<dim3(32, 2), 256>>>(pc2, conv3_w, conv3_b, pcp, 64);
    reduce_silu_kernel<<<1024, 256>>>(pcp, pc3, 262144, 2);
    conv3x3_s2_kernel<32, 256, 32, false><<<dim3(16, 4), 256>>>(pc3, conv4_w, conv4_b, pcp, 128);
    reduce_silu_kernel<<<512, 256>>>(pcp, pc4, 131072, 4);

    // 6. multi-scale avg pools into feat (channel offsets 0/32/96/224)
    pool_kernel<<<512, 256>>>(pc1, pfeat, 32, 128, 16, 0);
    pool_kernel<<<1024, 256>>>(pc2, pfeat, 64, 64, 8, 32);
    pool_kernel<<<2048, 256>>>(pc3, pfeat, 128, 32, 4, 96);
    pool_kernel<<<4096, 256>>>(pc4, pfeat, 256, 16, 2, 224);

    // 7. lin1 (480->128, 3x3 reflect, SiLU), split-K x30
    transpose_kernel<<<dim3(135, 4), dim3(32, 8)>>>(lin1_w, pwT);
    lin1_kernel<<<dim3(30, 8, 2), 128>>>(pfeat, pwT, plp);
    lin1_reduce_kernel<<<64, 256>>>(plp, lin1_b, ph1);

    // 8. lin2 (1x1, 128->27) + sigmoid
    lin2_kernel<<<14, 256>>>(ph1, lin2_w, lin2_b, pwl);

    // 9. fused upsample + LUT blend + clip
    final_kernel<<<dim3(1024, 4, 2), 256>>>(img, pwl, luts, out);
}

// round 3
// speedup vs baseline: 1.5171x; 1.5171x over previous
#include <cuda_runtime.h>
#include <math.h>

#define DINL __device__ __forceinline__
typedef unsigned long long ull;

DINL float silu_f(float x) { return x / (1.f + expf(-x)); }
DINL float sigm_f(float x) { return 1.f / (1.f + expf(-x)); }

// ---------------- packed f32x2 helpers (sm_100+) ----------------
DINL ull pk2(float x) { ull r; asm("mov.b64 %0,{%1,%1};" : "=l"(r) : "f"(x)); return r; }
DINL ull pkpair(float a, float b) { ull r; asm("mov.b64 %0,{%1,%2};" : "=l"(r) : "f"(a), "f"(b)); return r; }
DINL ull f2fma(ull a, ull b, ull c) {
    ull d; asm("fma.rn.f32x2 %0,%1,%2,%3;" : "=l"(d) : "l"(a), "l"(b), "l"(c)); return d;
}
DINL float2 upk(ull a) { float lo, hi; asm("mov.b64 {%0,%1},%2;" : "=f"(lo), "=f"(hi) : "l"(a)); return make_float2(lo, hi); }

// ------------------------- scratch (device globals) ------------------------
__device__ float g_x[2 * 3 * 256 * 256];
__device__ float g_c1[2 * 32 * 128 * 128];
__device__ float g_c2[2 * 64 * 64 * 64];
__device__ float g_c3[2 * 128 * 32 * 32];
__device__ float g_c4[2 * 256 * 16 * 16];
__device__ float g_feat[2 * 480 * 8 * 8];
__device__ float g_h1[2 * 128 * 8 * 8];
__device__ float g_wl[2 * 27 * 8 * 8];
__device__ float g_wT[4320 * 128];
__device__ float g_lpart[30 * 2 * 128 * 8 * 8];
__device__ float g_cpart[2097152];              // split-K partials (8MB)
__device__ float g_wrep[387936];                // repacked conv weights [ic][p][oc]

#define WR1_OFF 0
#define WR2_OFF 864
#define WR3_OFF 19296
#define WR4_OFF 93024

// ------------------------------ resize 1024->256 ---------------------------
__global__ void resize256_kernel(const float* __restrict__ img, float* __restrict__ out) {
    int idx = blockIdx.x * blockDim.x + threadIdx.x;
    if (idx >= 2 * 3 * 256 * 256) return;
    int ox = idx & 255;
    int oy = (idx >> 8) & 255;
    int bc = idx >> 16;
    const float scale = 1023.0f / 255.0f;
    float py = oy * scale;
    int iy = (int)py; if (iy > 1022) iy = 1022;
    float fy = py - (float)iy;
    float px = ox * scale;
    int ix = (int)px; if (ix > 1022) ix = 1022;
    float fx = px - (float)ix;
    const float* p = img + ((long)bc << 20) + iy * 1024 + ix;
    float v00 = p[0], v01 = p[1], v10 = p[1024], v11 = p[1025];
    float c0 = v00 + fy * (v10 - v00);
    float c1 = v01 + fy * (v11 - v01);
    out[idx] = c0 + fx * (c1 - c0);
}

// ------------------- conv weight repack: [oc][ic][p] -> [ic][p][oc] --------
__global__ void repack_w_kernel(const float* __restrict__ w, float* __restrict__ wrep,
                                int OC, int IC) {
    int idx = blockIdx.x * blockDim.x + threadIdx.x;
    int total = OC * IC * 9;
    if (idx >= total) return;
    int oc = idx % OC;
    int p = (idx / OC) % 9;
    int ic = idx / (OC * 9);
    wrep[idx] = w[(oc * IC + ic) * 9 + p];
}

// --------------- stride-2 3x3 conv, reflect pad, f32x2, split-K -------------
// Tile: 8 oc x 4 ow per thread (accs packed as 4 oc-pairs x 4 ow in f32x2).
template <int ICC, int OC, int H, bool FUSE>
__global__ __launch_bounds__(256, 2) void conv3x3_s2_v2(
    const float* __restrict__ in, const float* __restrict__ wrep,
    const float* __restrict__ bias, float* __restrict__ out, int ICtot) {
    constexpr int OH = H / 2;
    constexpr int OW = H / 2;
    constexpr int QW = OW / 4;
    constexpr int TOTAL = 2 * (OC / 8) * OH * QW;
    constexpr int NOUT = 2 * OC * OH * OW;
    int idx = blockIdx.x * 256 + threadIdx.x;
    if (idx >= TOTAL) return;
    int ks = blockIdx.y;
    int ic0 = ks * ICC;

    int q = idx % QW;
    int oh = (idx / QW) % OH;
    int ocg = (idx / (QW * OH)) % (OC / 8);
    int b = idx / (QW * OH * (OC / 8));
    int ow0 = q * 4;
    int oc0 = ocg * 8;
    int base = 2 * ow0;

    int rr[3];
#pragma unroll
    for (int kh = 0; kh < 3; kh++) { int r = 2 * oh - 1 + kh; rr[kh] = (r < 0) ? -r : r; }

    ull acc[4][4];
#pragma unroll
    for (int o2 = 0; o2 < 4; o2++) {
        ull bv = (ks == 0) ? pkpair(bias[oc0 + 2 * o2], bias[oc0 + 2 * o2 + 1]) : 0ull;
#pragma unroll
        for (int j = 0; j < 4; j++) acc[o2][j] = bv;
    }

    const float* wbase = wrep + (long)ic0 * 9 * OC + oc0;

    for (int ic = 0; ic < ICC; ic++) {
        const float* ip = in + (long)(b * ICtot + ic0 + ic) * H * H;
        const float* wp = wbase + (long)ic * 9 * OC;
#pragma unroll
        for (int kh = 0; kh < 3; kh++) {
            const float* rp = ip + rr[kh] * H;
            float v[10];  // cols base-2 .. base+7
            if (base) {
                const float2* r2 = (const float2*)(rp + base - 2);
#pragma unroll
                for (int t = 0; t < 5; t++) { float2 d = __ldg(r2 + t); v[2 * t] = d.x; v[2 * t + 1] = d.y; }
            } else {
                const float2* r2 = (const float2*)rp;
#pragma unroll
                for (int t = 0; t < 4; t++) { float2 d = __ldg(r2 + t); v[2 + 2 * t] = d.x; v[3 + 2 * t] = d.y; }
                v[1] = v[3];  // reflect: col -1 -> col 1
                v[0] = 0.f;
            }
            ull xx[9];
#pragma unroll
            for (int i = 0; i < 9; i++) xx[i] = pk2(v[i + 1]);
#pragma unroll
            for (int kw = 0; kw < 3; kw++) {
                const ulonglong2* w2p = (const ulonglong2*)(wp + (kh * 3 + kw) * OC);
                ulonglong2 wa = __ldg(w2p);
                ulonglong2 wb = __ldg(w2p + 1);
                ull wv[4] = {wa.x, wa.y, wb.x, wb.y};
#pragma unroll
                for (int o2 = 0; o2 < 4; o2++)
#pragma unroll
                    for (int j = 0; j < 4; j++)
                        acc[o2][j] = f2fma(wv[o2], xx[2 * j + kw], acc[o2][j]);
            }
        }
    }

    float* ob = out + (FUSE ? 0l : (long)ks * NOUT);
#pragma unroll
    for (int o2 = 0; o2 < 4; o2++) {
        float2 p0 = upk(acc[o2][0]), p1 = upk(acc[o2][1]), p2 = upk(acc[o2][2]), p3 = upk(acc[o2][3]);
        float ev0 = p0.x, ev1 = p1.x, ev2 = p2.x, ev3 = p3.x;
        float od0 = p0.y, od1 = p1.y, od2 = p2.y, od3 = p3.y;
        if (FUSE) {
            ev0 = silu_f(ev0); ev1 = silu_f(ev1); ev2 = silu_f(ev2); ev3 = silu_f(ev3);
            od0 = silu_f(od0); od1 = silu_f(od1); od2 = silu_f(od2); od3 = silu_f(od3);
        }
        long oe = ((long)(b * OC + oc0 + 2 * o2) * OH + oh) * OW + ow0;
        *(float4*)(ob + oe) = make_float4(ev0, ev1, ev2, ev3);
        *(float4*)(ob + oe + (long)OH * OW) = make_float4(od0, od1, od2, od3);
    }
}

// ----------------------- split-K reduce + SiLU epilogue ---------------------
__global__ void reduce_silu_kernel(const float* __restrict__ part, float* __restrict__ out,
                                   int n, int ks) {
    int idx = blockIdx.x * blockDim.x + threadIdx.x;
    if (idx >= n) return;
    float s = 0.f;
    for (int k = 0; k < ks; k++) s += part[k * n + idx];
    out[idx] = silu_f(s);
}

// ------------------------------ avg pool ------------------------------------
__global__ void pool_kernel(const float* __restrict__ in, float* __restrict__ feat,
                            int C, int H, int k, int coff) {
    int gw = (blockIdx.x * blockDim.x + threadIdx.x) >> 5;
    int lane = threadIdx.x & 31;
    int nout = 2 * C * 64;
    if (gw >= nout) return;
    int x = gw & 7;
    int y = (gw >> 3) & 7;
    int c = (gw >> 6) % C;
    int b = gw / (C * 64);
    const float* base = in + ((long)(b * C + c) * H + y * k) * H + x * k;
    float s = 0.f;
    int kk = k * k;
    for (int i = lane; i < kk; i += 32) s += base[(i / k) * H + (i % k)];
#pragma unroll
    for (int off = 16; off > 0; off >>= 1) s += __shfl_down_sync(0xffffffffu, s, off);
    if (lane == 0) feat[((b * 480 + coff + c) * 8 + y) * 8 + x] = s * (1.f / (float)kk);
}

// --------------------------- lin1 weight transpose --------------------------
__global__ void transpose_kernel(const float* __restrict__ w, float* __restrict__ wT) {
    __shared__ float tile[32][33];
    int bx = blockIdx.x;
    int by = blockIdx.y;
    int tx = threadIdx.x, ty = threadIdx.y;
#pragma unroll
    for (int i = 0; i < 4; i++)
        tile[ty + i * 8][tx] = w[(long)(by * 32 + ty + i * 8) * 4320 + bx * 32 + tx];
    __syncthreads();
#pragma unroll
    for (int i = 0; i < 4; i++)
        wT[(long)(bx * 32 + ty + i * 8) * 128 + by * 32 + tx] = tile[tx][ty + i * 8];
}

// ----------------- lin1: 3x3 reflect conv 480->128 on 8x8 -------------------
__global__ __launch_bounds__(128) void lin1_kernel(const float* __restrict__ feat,
                                                   const float* __restrict__ wT,
                                                   float* __restrict__ part) {
    __shared__ float slab[16 * 3 * 8];
    int kc = blockIdx.x;
    int oh = blockIdx.y;
    int b = blockIdx.z;
    int t = threadIdx.x;
    int ic0 = kc * 16;

    int ihs[3];
#pragma unroll
    for (int kh = 0; kh < 3; kh++) {
        int r = oh - 1 + kh;
        if (r < 0) r = -r;
        if (r > 7) r = 14 - r;
        ihs[kh] = r;
    }
    for (int j = t; j < 384; j += 128) {
        int icl = j / 24;
        int rem = j % 24;
        int r = rem / 8, col = rem % 8;
        slab[j] = feat[((b * 480 + ic0 + icl) * 8 + ihs[r]) * 8 + col];
    }
    __syncthreads();

    float acc[8];
#pragma unroll
    for (int ow = 0; ow < 8; ow++) acc[ow] = 0.f;

    const int IWT[10] = {1, 0, 1, 2, 3, 4, 5, 6, 7, 6};
#pragma unroll 2
    for (int icl = 0; icl < 16; icl++) {
        float rv[3][8];
#pragma unroll
        for (int r = 0; r < 3; r++)
#pragma unroll
            for (int col = 0; col < 8; col++) rv[r][col] = slab[icl * 24 + r * 8 + col];
#pragma unroll
        for (int kh = 0; kh < 3; kh++)
#pragma unroll
            for (int kw = 0; kw < 3; kw++) {
                float wv = __ldg(wT + (long)((ic0 + icl) * 9 + kh * 3 + kw) * 128 + t);
#pragma unroll
                for (int ow = 0; ow < 8; ow++) acc[ow] += wv * rv[kh][IWT[ow + kw]];
            }
    }
    int base = (((kc * 2 + b) * 128 + t) * 8 + oh) * 8;
#pragma unroll
    for (int ow = 0; ow < 8; ow++) part[base + ow] = acc[ow];
}

__global__ void lin1_reduce_kernel(const float* __restrict__ part,
                                   const float* __restrict__ bias, float* __restrict__ h1) {
    int idx = blockIdx.x * blockDim.x + threadIdx.x;
    if (idx >= 16384) return;
    int oc = (idx >> 6) & 127;
    float s = bias[oc];
#pragma unroll 6
    for (int kc = 0; kc < 30; kc++) s += part[kc * 16384 + idx];
    h1[idx] = silu_f(s);
}

// ------------------- lin2: 1x1 conv 128->27 + sigmoid -----------------------
__global__ void lin2_kernel(const float* __restrict__ h1, const float* __restrict__ w,
                            const float* __restrict__ bias, float* __restrict__ wl) {
    int idx = blockIdx.x * blockDim.x + threadIdx.x;
    if (idx >= 2 * 27 * 64) return;
    int pos = idx % 64;
    int oc = (idx / 64) % 27;
    int b = idx / (64 * 27);
    float acc = bias[oc];
    const float* hp = h1 + b * 128 * 64 + pos;
    const float* wp = w + oc * 128;
#pragma unroll 8
    for (int ic = 0; ic < 128; ic++) acc += hp[ic * 64] * __ldg(wp + ic);
    wl[(b * 27 + oc) * 64 + pos] = sigm_f(acc);
}

// -------- final: upsample weights 8->1024 + LUT blend (LUT transposed) ------
__global__ __launch_bounds__(256) void final_v2(const float* __restrict__ img,
                                                const float* __restrict__ wl,
                                                const float* __restrict__ luts,
                                                float* __restrict__ out) {
    __shared__ float s_lut[3 * 256 * 12];  // [c][i][k pad 12]
    __shared__ float s_row[27 * 8];

    int h = blockIdx.x;
    int b = blockIdx.y;
    int tid = threadIdx.x;

    for (int j = tid; j < 6912; j += 256) {
        int c = j / 2304;
        int k = (j / 256) % 9;
        int i = j % 256;
        s_lut[(c * 256 + i) * 12 + k] = luts[j];
    }

    const float sc = 7.0f / 1023.0f;
    float ph = h * sc;
    int ih0 = (int)ph; if (ih0 > 6) ih0 = 6;
    float fh = ph - (float)ih0;
    if (tid < 216) {
        int ch = tid >> 3;
        int iw = tid & 7;
        float a = wl[((b * 27 + ch) * 8 + ih0) * 8 + iw];
        float c = wl[((b * 27 + ch) * 8 + ih0 + 1) * 8 + iw];
        s_row[tid] = a + fh * (c - a);
    }
    __syncthreads();

#pragma unroll
    for (int chunk = 0; chunk < 4; chunk++) {
        int w = chunk * 256 + tid;
        float pw = w * sc;
        int iw0 = (int)pw; if (iw0 > 6) iw0 = 6;
        float fw = pw - (float)iw0;

#pragma unroll
        for (int c = 0; c < 3; c++) {
            long ibase = ((long)(b * 3 + c) << 20) + ((long)h << 10) + w;
            float v = img[ibase];
            float p = fminf(fmaxf(v, 0.f), 1.f) * 255.0f;
            int i0 = (int)p; if (i0 > 254) i0 = 254;
            float fr = p - (float)i0;

            const float4* lp = (const float4*)(s_lut + (c * 256 + i0) * 12);
            float4 A0 = lp[0], A1 = lp[1], A2 = lp[2];       // lut[k][i0]
            float4 B0 = lp[3], B1 = lp[4], B2 = lp[5];       // lut[k][i0+1]
            float l0k[9] = {A0.x, A0.y, A0.z, A0.w, A1.x, A1.y, A1.z, A1.w, A2.x};
            float l1k[9] = {B0.x, B0.y, B0.z, B0.w, B1.x, B1.y, B1.z, B1.w, B2.x};

            float acc = 0.f;
#pragma unroll
            for (int k = 0; k < 9; k++) {
                float lv = l0k[k] + fr * (l1k[k] - l0k[k]);
                int ch = c * 9 + k;
                float r0 = s_row[ch * 8 + iw0];
                float r1 = s_row[ch * 8 + iw0 + 1];
                float wv = r0 + fw * (r1 - r0);
                acc += wv * lv;
            }
            out[ibase] = fminf(fmaxf(acc, 0.f), 1.f);
        }
    }
}

// --------------------------------- launch ----------------------------------
extern "C" void kernel_launch(void* const* d_in, const int* in_sizes, int n_in,
                              void* d_out, int out_size) {
    const float* img     = (const float*)d_in[0];
    const float* conv1_w = (const float*)d_in[1];
    const float* conv1_b = (const float*)d_in[2];
    const float* conv2_w = (const float*)d_in[3];
    const float* conv2_b = (const float*)d_in[4];
    const float* conv3_w = (const float*)d_in[5];
    const float* conv3_b = (const float*)d_in[6];
    const float* conv4_w = (const float*)d_in[7];
    const float* conv4_b = (const float*)d_in[8];
    const float* lin1_w  = (const float*)d_in[9];
    const float* lin1_b  = (const float*)d_in[10];
    const float* lin2_w  = (const float*)d_in[11];
    const float* lin2_b  = (const float*)d_in[12];
    const float* luts    = (const float*)d_in[13];
    float* out = (float*)d_out;

    float *px, *pc1, *pc2, *pc3, *pc4, *pfeat, *ph1, *pwl, *pwT, *plp, *pcp, *pwr;
    cudaGetSymbolAddress((void**)&px, g_x);
    cudaGetSymbolAddress((void**)&pc1, g_c1);
    cudaGetSymbolAddress((void**)&pc2, g_c2);
    cudaGetSymbolAddress((void**)&pc3, g_c3);
    cudaGetSymbolAddress((void**)&pc4, g_c4);
    cudaGetSymbolAddress((void**)&pfeat, g_feat);
    cudaGetSymbolAddress((void**)&ph1, g_h1);
    cudaGetSymbolAddress((void**)&pwl, g_wl);
    cudaGetSymbolAddress((void**)&pwT, g_wT);
    cudaGetSymbolAddress((void**)&plp, g_lpart);
    cudaGetSymbolAddress((void**)&pcp, g_cpart);
    cudaGetSymbolAddress((void**)&pwr, g_wrep);

    // weight repacks (cheap, keeps kernel_launch deterministic)
    repack_w_kernel<<<(32 * 3 * 9 + 255) / 256, 256>>>(conv1_w, pwr + WR1_OFF, 32, 3);
    repack_w_kernel<<<(64 * 32 * 9 + 255) / 256, 256>>>(conv2_w, pwr + WR2_OFF, 64, 32);
    repack_w_kernel<<<(128 * 64 * 9 + 255) / 256, 256>>>(conv3_w, pwr + WR3_OFF, 128, 64);
    repack_w_kernel<<<(256 * 128 * 9 + 255) / 256, 256>>>(conv4_w, pwr + WR4_OFF, 256, 128);

    // 1. resize 1024 -> 256
    resize256_kernel<<<1536, 256>>>(img, px);

    // 2-5. conv stack (stride-2, reflect pad, SiLU), split-K for parallelism
    conv3x3_s2_v2<3, 32, 256, true><<<dim3(128, 1), 256>>>(px, pwr + WR1_OFF, conv1_b, pc1, 3);

    conv3x3_s2_v2<8, 64, 128, false><<<dim3(64, 4), 256>>>(pc1, pwr + WR2_OFF, conv2_b, pcp, 32);
    reduce_silu_kernel<<<2048, 256>>>(pcp, pc2, 524288, 4);

    conv3x3_s2_v2<8, 128, 64, false><<<dim3(32, 8), 256>>>(pc2, pwr + WR3_OFF, conv3_b, pcp, 64);
    reduce_silu_kernel<<<1024, 256>>>(pcp, pc3, 262144, 8);

    conv3x3_s2_v2<8, 256, 32, false><<<dim3(16, 16), 256>>>(pc3, pwr + WR4_OFF, conv4_b, pcp, 128);
    reduce_silu_kernel<<<512, 256>>>(pcp, pc4, 131072, 16);

    // 6. multi-scale avg pools
    pool_kernel<<<512, 256>>>(pc1, pfeat, 32, 128, 16, 0);
    pool_kernel<<<1024, 256>>>(pc2, pfeat, 64, 64, 8, 32);
    pool_kernel<<<2048, 256>>>(pc3, pfeat, 128, 32, 4, 96);
    pool_kernel<<<4096, 256>>>(pc4, pfeat, 256, 16, 2, 224);

    // 7. lin1 (480->128, 3x3 reflect, SiLU), split-K x30
    transpose_kernel<<<dim3(135, 4), dim3(32, 8)>>>(lin1_w, pwT);
    lin1_kernel<<<dim3(30, 8, 2), 128>>>(pfeat, pwT, plp);
    lin1_reduce_kernel<<<64, 256>>>(plp, lin1_b, ph1);

    // 8. lin2 (1x1, 128->27) + sigmoid
    lin2_kernel<<<14, 256>>>(ph1, lin2_w, lin2_b, pwl);

    // 9. fused upsample + LUT blend + clip
    final_v2<<<dim3(1024, 2), 256>>>(img, pwl, luts, out);
}

// round 4
// speedup vs baseline: 1.9835x; 1.3074x over previous
#include <cuda_runtime.h>
#include <math.h>

#define DINL __device__ __forceinline__
typedef unsigned long long ull;

DINL float silu_f(float x) { return x / (1.f + expf(-x)); }
DINL float sigm_f(float x) { return 1.f / (1.f + expf(-x)); }

// ---------------- packed f32x2 helpers (sm_100+) ----------------
DINL ull pk2(float x) { ull r; asm("mov.b64 %0,{%1,%1};" : "=l"(r) : "f"(x)); return r; }
DINL ull pkpair(float a, float b) { ull r; asm("mov.b64 %0,{%1,%2};" : "=l"(r) : "f"(a), "f"(b)); return r; }
DINL ull f2fma(ull a, ull b, ull c) {
    ull d; asm("fma.rn.f32x2 %0,%1,%2,%3;" : "=l"(d) : "l"(a), "l"(b), "l"(c)); return d;
}
DINL float2 upk(ull a) { float lo, hi; asm("mov.b64 {%0,%1},%2;" : "=f"(lo), "=f"(hi) : "l"(a)); return make_float2(lo, hi); }

// ------------------------- scratch (device globals) ------------------------
__device__ float g_x[2 * 3 * 256 * 256];
__device__ float g_c1[2 * 32 * 128 * 128];
__device__ float g_c2[2 * 64 * 64 * 64];
__device__ float g_c3[2 * 128 * 32 * 32];
__device__ float g_c4[2 * 256 * 16 * 16];
__device__ float g_feat[2 * 480 * 8 * 8];
__device__ float g_h1[2 * 128 * 8 * 8];
__device__ float g_wl[2 * 27 * 8 * 8];
__device__ float g_wT[4320 * 128];
__device__ float g_lpart[30 * 2 * 128 * 8 * 8];
__device__ float g_cpart[2097152];
__device__ float g_wrep[387936];
__device__ float g_G[2 * 3 * 8 * 8 * 256 * 2];   // fused weight*LUT table (G0, dG)

#define WR1_OFF 0
#define WR2_OFF 864
#define WR3_OFF 19296
#define WR4_OFF 93024

// ---------------- prep: all conv weight repacks + lin1 transpose -----------
// repack [oc][ic][p] -> [ic][p][oc]; transpose lin1_w [oc][k] -> [k][oc]
__global__ void prep_kernel(const float* __restrict__ w1, const float* __restrict__ w2,
                            const float* __restrict__ w3, const float* __restrict__ w4,
                            const float* __restrict__ lw, float* __restrict__ wrep,
                            float* __restrict__ wT) {
    int idx = blockIdx.x * 256 + threadIdx.x;
    if (idx < 864) {
        int oc = idx % 32, p = (idx / 32) % 9, ic = idx / 288;
        wrep[WR1_OFF + idx] = w1[(oc * 3 + ic) * 9 + p];
    } else if (idx < 864 + 18432) {
        int j = idx - 864;
        int oc = j % 64, p = (j / 64) % 9, ic = j / 576;
        wrep[WR2_OFF + j] = w2[(oc * 32 + ic) * 9 + p];
    } else if (idx < 19296 + 73728) {
        int j = idx - 19296;
        int oc = j % 128, p = (j / 128) % 9, ic = j / 1152;
        wrep[WR3_OFF + j] = w3[(oc * 64 + ic) * 9 + p];
    } else if (idx < 93024 + 294912) {
        int j = idx - 93024;
        int oc = j % 256, p = (j / 256) % 9, ic = j / 2304;
        wrep[WR4_OFF + j] = w4[(oc * 128 + ic) * 9 + p];
    } else if (idx < 387936 + 552960) {
        int j = idx - 387936;
        int k = j >> 7, oc = j & 127;
        wT[j] = lw[(long)oc * 4320 + k];
    }
}

// ------------------------------ resize 1024->256 ---------------------------
__global__ void resize256_kernel(const float* __restrict__ img, float* __restrict__ out) {
    int idx = blockIdx.x * blockDim.x + threadIdx.x;
    if (idx >= 2 * 3 * 256 * 256) return;
    int ox = idx & 255;
    int oy = (idx >> 8) & 255;
    int bc = idx >> 16;
    const float scale = 1023.0f / 255.0f;
    float py = oy * scale;
    int iy = (int)py; if (iy > 1022) iy = 1022;
    float fy = py - (float)iy;
    float px = ox * scale;
    int ix = (int)px; if (ix > 1022) ix = 1022;
    float fx = px - (float)ix;
    const float* p = img + ((long)bc << 20) + iy * 1024 + ix;
    float v00 = p[0], v01 = p[1], v10 = p[1024], v11 = p[1025];
    float c0 = v00 + fy * (v10 - v00);
    float c1 = v01 + fy * (v11 - v01);
    out[idx] = c0 + fx * (c1 - c0);
}

// --------------- stride-2 3x3 conv, reflect pad, f32x2, split-K -------------
template <int ICC, int OC, int H, bool FUSE>
__global__ __launch_bounds__(256, 2) void conv3x3_s2_v2(
    const float* __restrict__ in, const float* __restrict__ wrep,
    const float* __restrict__ bias, float* __restrict__ out, int ICtot) {
    constexpr int OH = H / 2;
    constexpr int OW = H / 2;
    constexpr int QW = OW / 4;
    constexpr int TOTAL = 2 * (OC / 8) * OH * QW;
    constexpr int NOUT = 2 * OC * OH * OW;
    int idx = blockIdx.x * 256 + threadIdx.x;
    if (idx >= TOTAL) return;
    int ks = blockIdx.y;
    int ic0 = ks * ICC;

    int q = idx % QW;
    int oh = (idx / QW) % OH;
    int ocg = (idx / (QW * OH)) % (OC / 8);
    int b = idx / (QW * OH * (OC / 8));
    int ow0 = q * 4;
    int oc0 = ocg * 8;
    int base = 2 * ow0;

    int rr[3];
#pragma unroll
    for (int kh = 0; kh < 3; kh++) { int r = 2 * oh - 1 + kh; rr[kh] = (r < 0) ? -r : r; }

    ull acc[4][4];
#pragma unroll
    for (int o2 = 0; o2 < 4; o2++) {
        ull bv = (ks == 0) ? pkpair(bias[oc0 + 2 * o2], bias[oc0 + 2 * o2 + 1]) : 0ull;
#pragma unroll
        for (int j = 0; j < 4; j++) acc[o2][j] = bv;
    }

    const float* wbase = wrep + (long)ic0 * 9 * OC + oc0;

    for (int ic = 0; ic < ICC; ic++) {
        const float* ip = in + (long)(b * ICtot + ic0 + ic) * H * H;
        const float* wp = wbase + (long)ic * 9 * OC;
#pragma unroll
        for (int kh = 0; kh < 3; kh++) {
            const float* rp = ip + rr[kh] * H;
            float v[10];
            if (base) {
                const float2* r2 = (const float2*)(rp + base - 2);
#pragma unroll
                for (int t = 0; t < 5; t++) { float2 d = __ldg(r2 + t); v[2 * t] = d.x; v[2 * t + 1] = d.y; }
            } else {
                const float2* r2 = (const float2*)rp;
#pragma unroll
                for (int t = 0; t < 4; t++) { float2 d = __ldg(r2 + t); v[2 + 2 * t] = d.x; v[3 + 2 * t] = d.y; }
                v[1] = v[3];
                v[0] = 0.f;
            }
            ull xx[9];
#pragma unroll
            for (int i = 0; i < 9; i++) xx[i] = pk2(v[i + 1]);
#pragma unroll
            for (int kw = 0; kw < 3; kw++) {
                const ulonglong2* w2p = (const ulonglong2*)(wp + (kh * 3 + kw) * OC);
                ulonglong2 wa = __ldg(w2p);
                ulonglong2 wb = __ldg(w2p + 1);
                ull wv[4] = {wa.x, wa.y, wb.x, wb.y};
#pragma unroll
                for (int o2 = 0; o2 < 4; o2++)
#pragma unroll
                    for (int j = 0; j < 4; j++)
                        acc[o2][j] = f2fma(wv[o2], xx[2 * j + kw], acc[o2][j]);
            }
        }
    }

    float* ob = out + (FUSE ? 0l : (long)ks * NOUT);
#pragma unroll
    for (int o2 = 0; o2 < 4; o2++) {
        float2 p0 = upk(acc[o2][0]), p1 = upk(acc[o2][1]), p2 = upk(acc[o2][2]), p3 = upk(acc[o2][3]);
        float ev0 = p0.x, ev1 = p1.x, ev2 = p2.x, ev3 = p3.x;
        float od0 = p0.y, od1 = p1.y, od2 = p2.y, od3 = p3.y;
        if (FUSE) {
            ev0 = silu_f(ev0); ev1 = silu_f(ev1); ev2 = silu_f(ev2); ev3 = silu_f(ev3);
            od0 = silu_f(od0); od1 = silu_f(od1); od2 = silu_f(od2); od3 = silu_f(od3);
        }
        long oe = ((long)(b * OC + oc0 + 2 * o2) * OH + oh) * OW + ow0;
        *(float4*)(ob + oe) = make_float4(ev0, ev1, ev2, ev3);
        *(float4*)(ob + oe + (long)OH * OW) = make_float4(od0, od1, od2, od3);
    }
}

// ----------------------- split-K reduce + SiLU epilogue ---------------------
__global__ void reduce_silu_kernel(const float* __restrict__ part, float* __restrict__ out,
                                   int n, int ks) {
    int idx = blockIdx.x * blockDim.x + threadIdx.x;
    if (idx >= n) return;
    float s = 0.f;
    for (int k = 0; k < ks; k++) s += part[k * n + idx];
    out[idx] = silu_f(s);
}

// ----------------------- merged avg pools (warp/output) ---------------------
__global__ void pool_all_kernel(const float* __restrict__ c1, const float* __restrict__ c2,
                                const float* __restrict__ c3, const float* __restrict__ c4,
                                float* __restrict__ feat) {
    int gw = (blockIdx.x * blockDim.x + threadIdx.x) >> 5;
    int lane = threadIdx.x & 31;
    if (gw >= 2 * 480 * 64) return;
    int x = gw & 7;
    int y = (gw >> 3) & 7;
    int cg = (gw >> 6) % 480;
    int b = gw / (480 * 64);
    const float* src; int C, H, k, c;
    if (cg < 32)       { src = c1; C = 32;  H = 128; k = 16; c = cg; }
    else if (cg < 96)  { src = c2; C = 64;  H = 64;  k = 8;  c = cg - 32; }
    else if (cg < 224) { src = c3; C = 128; H = 32;  k = 4;  c = cg - 96; }
    else               { src = c4; C = 256; H = 16;  k = 2;  c = cg - 224; }
    const float* base = src + ((long)(b * C + c) * H + y * k) * H + x * k;
    float s = 0.f;
    int kk = k * k;
    for (int i = lane; i < kk; i += 32) s += base[(i / k) * H + (i % k)];
#pragma unroll
    for (int off = 16; off > 0; off >>= 1) s += __shfl_down_sync(0xffffffffu, s, off);
    if (lane == 0) feat[((b * 480 + cg) * 8 + y) * 8 + x] = s * (1.f / (float)kk);
}

// ----------------- lin1: 3x3 reflect conv 480->128 on 8x8 -------------------
__global__ __launch_bounds__(128) void lin1_kernel(const float* __restrict__ feat,
                                                   const float* __restrict__ wT,
                                                   float* __restrict__ part) {
    __shared__ float slab[16 * 3 * 8];
    int kc = blockIdx.x;
    int oh = blockIdx.y;
    int b = blockIdx.z;
    int t = threadIdx.x;
    int ic0 = kc * 16;

    int ihs[3];
#pragma unroll
    for (int kh = 0; kh < 3; kh++) {
        int r = oh - 1 + kh;
        if (r < 0) r = -r;
        if (r > 7) r = 14 - r;
        ihs[kh] = r;
    }
    for (int j = t; j < 384; j += 128) {
        int icl = j / 24;
        int rem = j % 24;
        int r = rem / 8, col = rem % 8;
        slab[j] = feat[((b * 480 + ic0 + icl) * 8 + ihs[r]) * 8 + col];
    }
    __syncthreads();

    float acc[8];
#pragma unroll
    for (int ow = 0; ow < 8; ow++) acc[ow] = 0.f;

    const int IWT[10] = {1, 0, 1, 2, 3, 4, 5, 6, 7, 6};
#pragma unroll 2
    for (int icl = 0; icl < 16; icl++) {
        float rv[3][8];
#pragma unroll
        for (int r = 0; r < 3; r++)
#pragma unroll
            for (int col = 0; col < 8; col++) rv[r][col] = slab[icl * 24 + r * 8 + col];
#pragma unroll
        for (int kh = 0; kh < 3; kh++)
#pragma unroll
            for (int kw = 0; kw < 3; kw++) {
                float wv = __ldg(wT + (long)((ic0 + icl) * 9 + kh * 3 + kw) * 128 + t);
#pragma unroll
                for (int ow = 0; ow < 8; ow++) acc[ow] += wv * rv[kh][IWT[ow + kw]];
            }
    }
    int base = (((kc * 2 + b) * 128 + t) * 8 + oh) * 8;
#pragma unroll
    for (int ow = 0; ow < 8; ow++) part[base + ow] = acc[ow];
}

__global__ void lin1_reduce_kernel(const float* __restrict__ part,
                                   const float* __restrict__ bias, float* __restrict__ h1) {
    int idx = blockIdx.x * blockDim.x + threadIdx.x;
    if (idx >= 16384) return;
    int oc = (idx >> 6) & 127;
    float s = bias[oc];
#pragma unroll 6
    for (int kc = 0; kc < 30; kc++) s += part[kc * 16384 + idx];
    h1[idx] = silu_f(s);
}

// ------------------- lin2: 1x1 conv 128->27 + sigmoid -----------------------
__global__ void lin2_kernel(const float* __restrict__ h1, const float* __restrict__ w,
                            const float* __restrict__ bias, float* __restrict__ wl) {
    int idx = blockIdx.x * blockDim.x + threadIdx.x;
    if (idx >= 2 * 27 * 64) return;
    int pos = idx % 64;
    int oc = (idx / 64) % 27;
    int b = idx / (64 * 27);
    float acc = bias[oc];
    const float* hp = h1 + b * 128 * 64 + pos;
    const float* wp = w + oc * 128;
#pragma unroll 8
    for (int ic = 0; ic < 128; ic++) acc += hp[ic * 64] * __ldg(wp + ic);
    wl[(b * 27 + oc) * 64 + pos] = sigm_f(acc);
}

// ---------- G table: G_c(gy,gx,i) = sum_k wl[c*9+k](gy,gx) * lut[c,k,i] -----
// stored as (G0, dG) pairs: g_G[b][c][gy][gx][i][2]
__global__ void gprep_kernel(const float* __restrict__ wl, const float* __restrict__ luts,
                             float* __restrict__ G) {
    int gy = blockIdx.x & 7;
    int c = (blockIdx.x >> 3) % 3;
    int b = blockIdx.x / 24;
    __shared__ float wk[9][8];
    int tid = threadIdx.x;
    if (tid < 72) {
        int k = tid >> 3, gx = tid & 7;
        wk[k][gx] = wl[(b * 27 + c * 9 + k) * 64 + gy * 8 + gx];
    }
    __syncthreads();
    for (int j = tid; j < 2048; j += 256) {
        int gx = j >> 8;
        int i = j & 255;
        float g0 = 0.f, g1 = 0.f;
#pragma unroll
        for (int k = 0; k < 9; k++) {
            const float* lp = luts + (c * 9 + k) * 256;
            float l0 = lp[i];
            float l1 = (i < 255) ? lp[i + 1] : l0;
            g0 = fmaf(wk[k][gx], l0, g0);
            g1 = fmaf(wk[k][gx], l1, g1);
        }
        long o = ((((long)(b * 3 + c) * 8 + gy) * 8 + gx) * 256 + i) * 2;
        G[o] = g0;
        G[o + 1] = g1 - g0;
    }
}

// --------- final: per-pixel 4-corner gather from fused G table --------------
// block = 16 rows x full width; stages 3 gy-rows of G (3c x 3gy x 8gx x 256 x 2)
__global__ __launch_bounds__(512) void final_v3(const float* __restrict__ img,
                                                const float* __restrict__ G,
                                                float* __restrict__ out) {
    extern __shared__ float sG[];  // 36864 floats = 147456 B
    int rg = blockIdx.x;   // 0..63
    int b = blockIdx.y;
    int tid = threadIdx.x;
    int h0 = rg * 16;
    const float sc = 7.0f / 1023.0f;

    int g0row = (int)(h0 * sc); if (g0row > 6) g0row = 6;
    int gy_base = (g0row > 5) ? 5 : g0row;

    // stage 3 gy rows per channel: 9 x (8*256*2 floats) via float4
    for (int j = tid; j < 9216; j += 512) {
        int cg = j / 1024;            // c*3 + gyl
        int r = j % 1024;
        int c = cg / 3, gyl = cg % 3;
        long src = (((long)(b * 3 + c) * 8 + (gy_base + gyl)) * 8) * 512;  // floats
        ((float4*)sG)[cg * 1024 + r] = *(const float4*)(G + src + r * 4);
    }
    __syncthreads();

    // per-thread fixed columns
    int w0 = tid * 2;
    int gxp[2]; float fwp[2];
#pragma unroll
    for (int px = 0; px < 2; px++) {
        float pwv = (w0 + px) * sc;
        int gx = (int)pwv; if (gx > 6) gx = 6;
        gxp[px] = gx;
        fwp[px] = pwv - (float)gx;
    }

    const float2* sgp = (const float2*)sG;

    for (int r = 0; r < 16; r++) {
        int h = h0 + r;
        float ph = h * sc;
        int gy0 = (int)ph; if (gy0 > 6) gy0 = 6;
        float fh = ph - (float)gy0;
        int gyl = gy0 - gy_base;

#pragma unroll
        for (int c = 0; c < 3; c++) {
            long ib = ((long)(b * 3 + c) << 20) + ((long)h << 10) + w0;
            float2 iv = *(const float2*)(img + ib);
            float2 res;
            const float2* crow = sgp + (c * 3 + gyl) * 2048;
#pragma unroll
            for (int px = 0; px < 2; px++) {
                float v = px ? iv.y : iv.x;
                float p = fminf(fmaxf(v, 0.f), 1.f) * 255.0f;
                int i0 = (int)p; if (i0 > 254) i0 = 254;
                float fr = p - (float)i0;
                const float2* b00 = crow + gxp[px] * 256;
                float2 A = b00[i0];
                float2 Bv = b00[256 + i0];
                float2 Cv = b00[2048 + i0];
                float2 Dv = b00[2048 + 256 + i0];
                float va = fmaf(fr, A.y, A.x);
                float vb = fmaf(fr, Bv.y, Bv.x);
                float vc = fmaf(fr, Cv.y, Cv.x);
                float vd = fmaf(fr, Dv.y, Dv.x);
                float fw = fwp[px];
                float top = fmaf(fw, vb - va, va);
                float bot = fmaf(fw, vd - vc, vc);
                float rv = fmaf(fh, bot - top, top);
                rv = fminf(fmaxf(rv, 0.f), 1.f);
                if (px) res.y = rv; else res.x = rv;
            }
            *(float2*)(out + ib) = res;
        }
    }
}

// --------------------------------- launch ----------------------------------
extern "C" void kernel_launch(void* const* d_in, const int* in_sizes, int n_in,
                              void* d_out, int out_size) {
    const float* img     = (const float*)d_in[0];
    const float* conv1_w = (const float*)d_in[1];
    const float* conv1_b = (const float*)d_in[2];
    const float* conv2_w = (const float*)d_in[3];
    const float* conv2_b = (const float*)d_in[4];
    const float* conv3_w = (const float*)d_in[5];
    const float* conv3_b = (const float*)d_in[6];
    const float* conv4_w = (const float*)d_in[7];
    const float* conv4_b = (const float*)d_in[8];
    const float* lin1_w  = (const float*)d_in[9];
    const float* lin1_b  = (const float*)d_in[10];
    const float* lin2_w  = (const float*)d_in[11];
    const float* lin2_b  = (const float*)d_in[12];
    const float* luts    = (const float*)d_in[13];
    float* out = (float*)d_out;

    float *px, *pc1, *pc2, *pc3, *pc4, *pfeat, *ph1, *pwl, *pwT, *plp, *pcp, *pwr, *pG;
    cudaGetSymbolAddress((void**)&px, g_x);
    cudaGetSymbolAddress((void**)&pc1, g_c1);
    cudaGetSymbolAddress((void**)&pc2, g_c2);
    cudaGetSymbolAddress((void**)&pc3, g_c3);
    cudaGetSymbolAddress((void**)&pc4, g_c4);
    cudaGetSymbolAddress((void**)&pfeat, g_feat);
    cudaGetSymbolAddress((void**)&ph1, g_h1);
    cudaGetSymbolAddress((void**)&pwl, g_wl);
    cudaGetSymbolAddress((void**)&pwT, g_wT);
    cudaGetSymbolAddress((void**)&plp, g_lpart);
    cudaGetSymbolAddress((void**)&pcp, g_cpart);
    cudaGetSymbolAddress((void**)&pwr, g_wrep);
    cudaGetSymbolAddress((void**)&pG, g_G);

    static bool attr_set = false;
    // (setting an attribute is idempotent & deterministic; not a graph op)
    cudaFuncSetAttribute(final_v3, cudaFuncAttributeMaxDynamicSharedMemorySize, 147456);
    (void)attr_set;

    // 0. prep: weight repacks + lin1 transpose (one kernel)
    prep_kernel<<<3676, 256>>>(conv1_w, conv2_w, conv3_w, conv4_w, lin1_w, pwr, pwT);

    // 1. resize 1024 -> 256
    resize256_kernel<<<1536, 256>>>(img, px);

    // 2-5. conv stack (stride-2, reflect pad, SiLU), split-K
    conv3x3_s2_v2<3, 32, 256, true><<<dim3(128, 1), 256>>>(px, pwr + WR1_OFF, conv1_b, pc1, 3);

    conv3x3_s2_v2<8, 64, 128, false><<<dim3(64, 4), 256>>>(pc1, pwr + WR2_OFF, conv2_b, pcp, 32);
    reduce_silu_kernel<<<2048, 256>>>(pcp, pc2, 524288, 4);

    conv3x3_s2_v2<8, 128, 64, false><<<dim3(32, 8), 256>>>(pc2, pwr + WR3_OFF, conv3_b, pcp, 64);
    reduce_silu_kernel<<<1024, 256>>>(pcp, pc3, 262144, 8);

    conv3x3_s2_v2<8, 256, 32, false><<<dim3(16, 16), 256>>>(pc3, pwr + WR4_OFF, conv4_b, pcp, 128);
    reduce_silu_kernel<<<512, 256>>>(pcp, pc4, 131072, 16);

    // 6. merged multi-scale avg pools
    pool_all_kernel<<<7680, 256>>>(pc1, pc2, pc3, pc4, pfeat);

    // 7. lin1 (480->128, 3x3 reflect, SiLU), split-K x30
    lin1_kernel<<<dim3(30, 8, 2), 128>>>(pfeat, pwT, plp);
    lin1_reduce_kernel<<<64, 256>>>(plp, lin1_b, ph1);

    // 8. lin2 (1x1, 128->27) + sigmoid
    lin2_kernel<<<14, 256>>>(ph1, lin2_w, lin2_b, pwl);

    // 9. fuse weights into LUT table
    gprep_kernel<<<48, 256>>>(pwl, luts, pG);

    // 10. final: 4-corner gather + clip
    final_v3<<<dim3(64, 2), 512, 147456>>>(img, pG, out);
}